// round 11
// baseline (speedup 1.0000x reference)
#include <cuda_runtime.h>
#include <cuda_fp16.h>
#include <math.h>
#include <stdint.h>

// Problem constants
#define BB 8
#define CC 512
#define NN 2304          // 48*48
#define NPROJ 1536       // q(512) | interleaved k,v (1024)
#define NKV 1024         // interleaved pairs: col 2c=ekv_c, 2c+1=ek_c
#define MGT 144          // NN/16 m-groups
#define KOCT_P 32        // CC/16 k-octs (projection K)
#define KOCT_A 144       // NN/16 k-octs (attention K)

// ---------------------------------------------------------------------------
// Scratch — MMA-native layouts (validated in R10).
// A-native: uint4 at [koct][mg][lane] = full m16k16 A-frag.
// B-native: uint2 at [koct][n][lq]   = full k16n8 B-frag.
// ---------------------------------------------------------------------------
__device__ uint4 g_x4 [(size_t)BB * KOCT_P * MGT * 32];
__device__ uint4 g_y4 [(size_t)BB * KOCT_P * MGT * 32];
__device__ uint4 g_eb4[(size_t)KOCT_A * MGT * 32];
__device__ uint2 g_w2 [(size_t)KOCT_P * NPROJ * 4];
__device__ uint2 g_kv2[(size_t)BB * KOCT_A * NKV * 4];
__device__ float g_sq [(size_t)BB * NN * CC];

// ---------------------------------------------------------------------------
// Helpers
// ---------------------------------------------------------------------------
__device__ __forceinline__ uint32_t packh2(float lo, float hi) {
    __half2 h = __floats2half2_rn(lo, hi);
    return *reinterpret_cast<uint32_t*>(&h);
}

__device__ __forceinline__ void mma_f16(float c[4], const uint32_t* a,
                                        const uint32_t* b) {
    asm volatile(
        "mma.sync.aligned.m16n8k16.row.col.f32.f16.f16.f32 "
        "{%0,%1,%2,%3},{%4,%5,%6,%7},{%8,%9},{%0,%1,%2,%3};\n"
        : "+f"(c[0]), "+f"(c[1]), "+f"(c[2]), "+f"(c[3])
        : "r"(a[0]), "r"(a[1]), "r"(a[2]), "r"(a[3]), "r"(b[0]), "r"(b[1]));
}

__device__ __forceinline__ uint32_t smem_u32(const void* p) {
    uint32_t a;
    asm("{ .reg .u64 t; cvta.to.shared.u64 t, %1; cvt.u32.u64 %0, t; }"
        : "=r"(a) : "l"(p));
    return a;
}

__device__ __forceinline__ void cp16(uint32_t saddr, const void* gptr) {
    asm volatile("cp.async.cg.shared.global [%0], [%1], 16;"
                 :: "r"(saddr), "l"(gptr));
}
#define CP_COMMIT() asm volatile("cp.async.commit_group;" ::: "memory")
#define CP_WAIT(n)  asm volatile("cp.async.wait_group %0;" :: "n"(n) : "memory")

// ---------------------------------------------------------------------------
// prep_all (fused): block ranges
//   [0,4608) x->A-native   [4608,9216) y->A-native
//   [9216,9984) W->B-native  [9984,12576) exp(pb)->A-native
// ---------------------------------------------------------------------------
#define PBLK_X  4608
#define PBLK_W  768
#define PBLK_EB 2592
#define PREP_BLOCKS (2 * PBLK_X + PBLK_W + PBLK_EB)   // 12576

__global__ void __launch_bounds__(256)
prep_all(const float* __restrict__ x, const float* __restrict__ y,
         const float* __restrict__ Wq, const float* __restrict__ Wk,
         const float* __restrict__ Wv, const float* __restrict__ pb) {
    __shared__ float s[16][132];
    const int tid = threadIdx.x;
    const int blk = blockIdx.x;

    if (blk < 2 * PBLK_X) {
        // x/y -> A-native (k = channel)
        const bool isx = blk < PBLK_X;
        const float* src = isx ? x : y;
        uint4* dst = isx ? g_x4 : g_y4;
        int v = isx ? blk : blk - PBLK_X;
        int b = v / 576, rem = v % 576;
        int koct = rem / 18, iblk = rem % 18;
        int i0 = iblk * 128, c0 = koct * 16;
        #pragma unroll
        for (int r = 0; r < 2; r++) {
            int idx = tid + r * 256;
            int row = idx >> 5, col4 = (idx & 31) << 2;
            float4 f = *(const float4*)(src + ((size_t)(b * CC + c0 + row)) * NN + i0 + col4);
            *(float4*)(&s[row][col4]) = f;
        }
        __syncthreads();
        const int mg = tid >> 5, lane = tid & 31, lr = lane >> 2, lq = lane & 3;
        const int m = mg * 16 + lr;
        uint4 o;
        o.x = packh2(s[2 * lq][m],     s[2 * lq + 1][m]);
        o.y = packh2(s[2 * lq][m + 8], s[2 * lq + 1][m + 8]);
        o.z = packh2(s[2 * lq + 8][m],     s[2 * lq + 9][m]);
        o.w = packh2(s[2 * lq + 8][m + 8], s[2 * lq + 9][m + 8]);
        dst[(((size_t)b * KOCT_P + koct) * MGT + iblk * 8 + mg) * 32 + lane] = o;
    } else if (blk < 2 * PBLK_X + PBLK_W) {
        // W -> B-native, n = q | k,v interleaved
        int idx = (blk - 2 * PBLK_X) * 256 + tid;
        int lq = idx & 3;
        int n  = (idx >> 2) % NPROJ;
        int koct = idx / (NPROJ * 4);
        const float* W;
        int c;
        if (n < 512) { W = Wq; c = n; }
        else {
            int m = n - 512;
            c = m >> 1;
            W = (m & 1) ? Wv : Wk;
        }
        int k0 = koct * 16 + 2 * lq;
        float2 lo = *(const float2*)(W + (size_t)c * CC + k0);
        float2 hi = *(const float2*)(W + (size_t)c * CC + k0 + 8);
        uint2 o;
        o.x = packh2(lo.x, lo.y);
        o.y = packh2(hi.x, hi.y);
        g_w2[idx] = o;
    } else {
        // exp(pb) -> A-native (m = i, k = j)
        int t = blk - (2 * PBLK_X + PBLK_W);
        int koct = t / 18, iblk = t % 18;
        int i0 = iblk * 128, j0 = koct * 16;
        #pragma unroll
        for (int r = 0; r < 2; r++) {
            int idx = tid + r * 256;
            int irow = idx >> 2, j4 = (idx & 3) << 2;
            float4 f = *(const float4*)(pb + (size_t)(i0 + irow) * NN + j0 + j4);
            s[j4 + 0][irow] = __expf(f.x);
            s[j4 + 1][irow] = __expf(f.y);
            s[j4 + 2][irow] = __expf(f.z);
            s[j4 + 3][irow] = __expf(f.w);
        }
        __syncthreads();
        const int mg = tid >> 5, lane = tid & 31, lr = lane >> 2, lq = lane & 3;
        const int m = mg * 16 + lr;
        uint4 o;
        o.x = packh2(s[2 * lq][m],     s[2 * lq + 1][m]);
        o.y = packh2(s[2 * lq][m + 8], s[2 * lq + 1][m + 8]);
        o.z = packh2(s[2 * lq + 8][m],     s[2 * lq + 9][m]);
        o.w = packh2(s[2 * lq + 8][m + 8], s[2 * lq + 9][m + 8]);
        g_eb4[((size_t)koct * MGT + iblk * 8 + mg) * 32 + lane] = o;
    }
}

// ---------------------------------------------------------------------------
// fp16 GEMM core: BM=128 BN=256, chunk = 4 k-octs (64 k), 256 thr,
// warps 2(m) x 4(n), warp tile 64x64, 3-stage cp.async ring.
// Per ka-step: 4x LDS.128 + 8x LDS.64 feed 32 HMMAs (0.375 LDS/MMA).
// ---------------------------------------------------------------------------
#define STG 3
#define A_ST 16384                       // 4 koct * 8 mg * 32 lanes * 16 B
#define B_ST 32768                       // 4 koct * 256 n * 4 lq * 8 B
#define GEMM_SMEM (STG * (A_ST + B_ST))  // 147456 B

template <int MODE>
__global__ void __launch_bounds__(256)
gemm_f16(const float* __restrict__ bq, const float* __restrict__ bk,
         const float* __restrict__ bv, float* __restrict__ out) {
    extern __shared__ char smem[];
    const uint32_t smb = smem_u32(smem);

    const int b  = blockIdx.z;
    const int m0 = blockIdx.x * 128;
    const int n0 = blockIdx.y * 256;
    const int tid = threadIdx.x;

    const uint4* Ag;
    const uint2* Bg;
    int Ntot, nch;
    if (MODE == 0) {
        Ag = ((blockIdx.y < 2) ? g_x4 : g_y4) + (size_t)b * KOCT_P * MGT * 32;
        Bg = g_w2;
        Ntot = NPROJ; nch = KOCT_P / 4;          // 8
    } else {
        Ag = g_eb4;
        Bg = g_kv2 + (size_t)b * KOCT_A * NKV * 4;
        Ntot = NKV; nch = KOCT_A / 4;            // 36
    }
    const int mg0 = m0 >> 4;

    const int wid = tid >> 5;
    const int mwg = (wid & 1) * 4;        // m-group base (4 mg = 64 rows/warp)
    const int nw  = (wid >> 1) * 64;      // 4 n-warps
    const int lane = tid & 31;
    const int lq = lane & 3;
    const int lr = lane >> 2;

    auto loadAsync = [&](int ch, int st) {
        const uint32_t sA = smb + st * A_ST;
        const uint32_t sB = smb + STG * A_ST + st * B_ST;
        #pragma unroll
        for (int r = 0; r < 4; r++) {
            int ko = ch * 4 + r;
            cp16(sA + r * 4096 + tid * 16,
                 Ag + ((size_t)ko * MGT + mg0) * 32 + tid);
            #pragma unroll
            for (int t = 0; t < 2; t++) {
                int ci = tid + t * 256;          // 512 x 16B per koct
                cp16(sB + r * 8192 + ci * 16,
                     Bg + ((size_t)ko * Ntot + n0) * 4 + ci * 2);
            }
        }
    };

    float acc[4][8][4];
    #pragma unroll
    for (int i = 0; i < 4; i++)
        #pragma unroll
        for (int j = 0; j < 8; j++)
            #pragma unroll
            for (int l = 0; l < 4; l++) acc[i][j][l] = 0.f;

    #pragma unroll
    for (int s = 0; s < STG - 1; s++) {
        loadAsync(s, s);
        CP_COMMIT();
    }

    int st = 0;
    for (int c = 0; c < nch; c++) {
        CP_WAIT(STG - 2);
        __syncthreads();
        if (c + STG - 1 < nch) loadAsync(c + STG - 1, (c + STG - 1) % STG);
        CP_COMMIT();

        const uint4* As4 = (const uint4*)(smem + st * A_ST);
        const uint2* Bs2 = (const uint2*)(smem + STG * A_ST + st * B_ST);
        #pragma unroll
        for (int ka = 0; ka < 4; ka++) {
            uint4 af[4];
            #pragma unroll
            for (int mi = 0; mi < 4; mi++)
                af[mi] = As4[ka * 256 + (mwg + mi) * 32 + lane];
            uint2 bf[8];
            #pragma unroll
            for (int ni = 0; ni < 8; ni++)
                bf[ni] = Bs2[ka * 1024 + (nw + ni * 8) * 4 + lane];
            #pragma unroll
            for (int mi = 0; mi < 4; mi++)
                #pragma unroll
                for (int ni = 0; ni < 8; ni++)
                    mma_f16(acc[mi][ni], (const uint32_t*)&af[mi],
                            (const uint32_t*)&bf[ni]);
        }
        st++;
        if (st == STG) st = 0;
    }

    // ------------------------------- Epilogues -----------------------------
    const int mw = (wid & 1) * 64;
    if (MODE == 0) {
        if (n0 < 512) {
            float* sq = g_sq + (size_t)b * NN * CC;
            #pragma unroll
            for (int mi = 0; mi < 4; mi++) {
                #pragma unroll
                for (int ni = 0; ni < 8; ni++) {
                    int row = m0 + mw + 16 * mi + lr;
                    int col = n0 + nw + 8 * ni + 2 * lq;
                    float b0 = bq[col], b1 = bq[col + 1];
                    float* a = acc[mi][ni];
                    float2 v0, v1;
                    v0.x = __fdividef(1.f, 1.f + __expf(-(a[0] + b0)));
                    v0.y = __fdividef(1.f, 1.f + __expf(-(a[1] + b1)));
                    v1.x = __fdividef(1.f, 1.f + __expf(-(a[2] + b0)));
                    v1.y = __fdividef(1.f, 1.f + __expf(-(a[3] + b1)));
                    *(float2*)(sq + (size_t)row * CC + col) = v0;
                    *(float2*)(sq + (size_t)(row + 8) * CC + col) = v1;
                }
            }
        } else {
            // kv region -> attn B-native [koct_j][c2][lq_j]
            uint2* kvh = g_kv2 + (size_t)b * KOCT_A * NKV * 4;
            const bool evenR = (lr & 1) == 0;
            const int t = lr >> 1;
            #pragma unroll
            for (int mi = 0; mi < 4; mi++) {
                int mb = m0 + mw + 16 * mi;
                int koct = mb >> 4;
                #pragma unroll
                for (int ni = 0; ni < 8; ni++) {
                    int col = n0 + nw + 8 * ni + 2 * lq - 512;   // even c2 (ekv)
                    int ch = col >> 1;
                    float bkc = bk[ch], bvc = bv[ch];
                    float* a = acc[mi][ni];
                    float e0  = __expf(a[0] + bkc);
                    float ev0 = e0 * (a[1] + bvc);
                    float e1  = __expf(a[2] + bkc);
                    float ev1 = e1 * (a[3] + bvc);
                    float pe0  = __shfl_xor_sync(0xffffffffu, e0, 4);
                    float pev0 = __shfl_xor_sync(0xffffffffu, ev0, 4);
                    float pe1  = __shfl_xor_sync(0xffffffffu, e1, 4);
                    float pev1 = __shfl_xor_sync(0xffffffffu, ev1, 4);
                    if (evenR) {
                        uint2 w0, w1;
                        w0.x = packh2(ev0, pev0);
                        w0.y = packh2(ev1, pev1);
                        w1.x = packh2(e0, pe0);
                        w1.y = packh2(e1, pe1);
                        kvh[((size_t)koct * NKV + col) * 4 + t]     = w0;
                        kvh[((size_t)koct * NKV + col + 1) * 4 + t] = w1;
                    }
                }
            }
        }
    } else {
        // attn: even col = num, odd = den -> sq * num/den -> transpose -> out
        __syncthreads();
        float* so = (float*)smem;     // [c_local 0..127][m_local 0..127] stride 136
        const float* sq = g_sq + (size_t)b * NN * CC;
        const int gc0 = n0 >> 1;      // 128 channels per CTA
        #pragma unroll
        for (int mi = 0; mi < 4; mi++) {
            #pragma unroll
            for (int ni = 0; ni < 8; ni++) {
                int rowm = mw + 16 * mi + lr;
                int cl = (nw >> 1) + 4 * ni + lq;    // 0..127
                int gi = m0 + rowm;
                int gc = gc0 + cl;
                float* a = acc[mi][ni];
                float s0 = sq[(size_t)gi * CC + gc];
                float s1 = sq[(size_t)(gi + 8) * CC + gc];
                so[cl * 136 + rowm]     = s0 * __fdividef(a[0], a[1]);
                so[cl * 136 + rowm + 8] = s1 * __fdividef(a[2], a[3]);
            }
        }
        __syncthreads();
        float* o = out + (size_t)b * CC * NN;
        #pragma unroll
        for (int r2 = 0; r2 < 16; r2++) {
            int v = tid + r2 * 256;
            int cl = v >> 5, m4 = (v & 31) << 2;
            float4 val = *(float4*)(so + cl * 136 + m4);
            *(float4*)(o + (size_t)(gc0 + cl) * NN + m0 + m4) = val;
        }
    }
}

// ---------------------------------------------------------------------------
// Launch.  Order: 0 prep_all, 1 proj, 2 attn
// ---------------------------------------------------------------------------
extern "C" void kernel_launch(void* const* d_in, const int* in_sizes, int n_in,
                              void* d_out, int out_size) {
    const float* x  = (const float*)d_in[0];
    const float* y  = (const float*)d_in[1];
    const float* Wq = (const float*)d_in[2];
    const float* bq = (const float*)d_in[3];
    const float* Wk = (const float*)d_in[4];
    const float* bk = (const float*)d_in[5];
    const float* Wv = (const float*)d_in[6];
    const float* bv = (const float*)d_in[7];
    const float* pb = (const float*)d_in[8];
    float* out = (float*)d_out;

    static bool attr_done = false;
    if (!attr_done) {
        cudaFuncSetAttribute(gemm_f16<0>,
                             cudaFuncAttributeMaxDynamicSharedMemorySize, GEMM_SMEM);
        cudaFuncSetAttribute(gemm_f16<1>,
                             cudaFuncAttributeMaxDynamicSharedMemorySize, GEMM_SMEM);
        attr_done = true;
    }

    // 0) all operand prep in one launch
    prep_all<<<PREP_BLOCKS, 256>>>(x, y, Wq, Wk, Wv, pb);

    // 1) fused projection GEMM -> g_sq, g_kv2 (attn B-native)
    {
        dim3 g(NN / 128, NPROJ / 256, BB);   // (18, 6, 8)
        gemm_f16<0><<<g, 256, GEMM_SMEM>>>(bq, bk, bv, nullptr);
    }

    // 2) attention GEMM + fused final epilogue -> out
    {
        dim3 g(NN / 128, NKV / 256, BB);     // (18, 4, 8)
        gemm_f16<1><<<g, 256, GEMM_SMEM>>>(bq, bk, bv, out);
    }
}

// round 12
// speedup vs baseline: 1.0475x; 1.0475x over previous
#include <cuda_runtime.h>
#include <cuda_fp16.h>
#include <math.h>
#include <stdint.h>

// Problem constants
#define BB 8
#define CC 512
#define NN 2304          // 48*48
#define NPROJ 1536       // q(512) | interleaved k,v (1024)
#define NKV 1024         // interleaved pairs: col 2c=ekv_c, 2c+1=ek_c
#define MGT 144          // NN/16 m-groups
#define KOCT_P 32        // CC/16 k-octs (projection K)
#define KOCT_A 144       // NN/16 k-octs (attention K)
#define NP16_P 96        // NPROJ/16 n-pairs
#define NP16_A 64        // NKV/16 n-pairs

// ---------------------------------------------------------------------------
// Scratch — MMA-native layouts.
// A-native: uint4 at [koct][mg][lane] = full m16k16 A-frag (R10-validated).
// B-paired: uint4 at [koct][pair][lane(lr*4+lq)] =
//   {h2(n,2lq..), h2(n,2lq+8..), h2(n+8,2lq..), h2(n+8,2lq+8..)}, n = pair*16+lr
//   = B-frags for n-blocks (n, n+8) in one 16B word.
// ---------------------------------------------------------------------------
__device__ uint4 g_x4 [(size_t)BB * KOCT_P * MGT * 32];
__device__ uint4 g_y4 [(size_t)BB * KOCT_P * MGT * 32];
__device__ uint4 g_eb4[(size_t)KOCT_A * MGT * 32];
__device__ uint4 g_w4 [(size_t)KOCT_P * NP16_P * 32];
__device__ uint4 g_kv4[(size_t)BB * KOCT_A * NP16_A * 32];
__device__ float g_sq [(size_t)BB * NN * CC];

// ---------------------------------------------------------------------------
// Helpers
// ---------------------------------------------------------------------------
__device__ __forceinline__ uint32_t packh2(float lo, float hi) {
    __half2 h = __floats2half2_rn(lo, hi);
    return *reinterpret_cast<uint32_t*>(&h);
}

__device__ __forceinline__ void mma_f16(float c[4], const uint32_t* a,
                                        const uint32_t* b) {
    asm volatile(
        "mma.sync.aligned.m16n8k16.row.col.f32.f16.f16.f32 "
        "{%0,%1,%2,%3},{%4,%5,%6,%7},{%8,%9},{%0,%1,%2,%3};\n"
        : "+f"(c[0]), "+f"(c[1]), "+f"(c[2]), "+f"(c[3])
        : "r"(a[0]), "r"(a[1]), "r"(a[2]), "r"(a[3]), "r"(b[0]), "r"(b[1]));
}

__device__ __forceinline__ uint32_t smem_u32(const void* p) {
    uint32_t a;
    asm("{ .reg .u64 t; cvta.to.shared.u64 t, %1; cvt.u32.u64 %0, t; }"
        : "=r"(a) : "l"(p));
    return a;
}

__device__ __forceinline__ void cp16(uint32_t saddr, const void* gptr) {
    asm volatile("cp.async.cg.shared.global [%0], [%1], 16;"
                 :: "r"(saddr), "l"(gptr));
}
#define CP_COMMIT() asm volatile("cp.async.commit_group;" ::: "memory")
#define CP_WAIT(n)  asm volatile("cp.async.wait_group %0;" :: "n"(n) : "memory")

// ---------------------------------------------------------------------------
// prep_all (fused): block ranges
//   [0,4608) x->A-native  [4608,9216) y->A-native
//   [9216,9600) W->B-paired  [9600,12192) exp(pb)->A-native
// ---------------------------------------------------------------------------
#define PBLK_X  4608
#define PBLK_W  384
#define PBLK_EB 2592
#define PREP_BLOCKS (2 * PBLK_X + PBLK_W + PBLK_EB)   // 12192

__global__ void __launch_bounds__(256)
prep_all(const float* __restrict__ x, const float* __restrict__ y,
         const float* __restrict__ Wq, const float* __restrict__ Wk,
         const float* __restrict__ Wv, const float* __restrict__ pb) {
    __shared__ float s[16][132];
    const int tid = threadIdx.x;
    const int blk = blockIdx.x;

    if (blk < 2 * PBLK_X) {
        // x/y -> A-native (k = channel)
        const bool isx = blk < PBLK_X;
        const float* src = isx ? x : y;
        uint4* dst = isx ? g_x4 : g_y4;
        int v = isx ? blk : blk - PBLK_X;
        int b = v / 576, rem = v % 576;
        int koct = rem / 18, iblk = rem % 18;
        int i0 = iblk * 128, c0 = koct * 16;
        #pragma unroll
        for (int r = 0; r < 2; r++) {
            int idx = tid + r * 256;
            int row = idx >> 5, col4 = (idx & 31) << 2;
            float4 f = *(const float4*)(src + ((size_t)(b * CC + c0 + row)) * NN + i0 + col4);
            *(float4*)(&s[row][col4]) = f;
        }
        __syncthreads();
        const int mg = tid >> 5, lane = tid & 31, lr = lane >> 2, lq = lane & 3;
        const int m = mg * 16 + lr;
        uint4 o;
        o.x = packh2(s[2 * lq][m],     s[2 * lq + 1][m]);
        o.y = packh2(s[2 * lq][m + 8], s[2 * lq + 1][m + 8]);
        o.z = packh2(s[2 * lq + 8][m],     s[2 * lq + 9][m]);
        o.w = packh2(s[2 * lq + 8][m + 8], s[2 * lq + 9][m + 8]);
        dst[(((size_t)b * KOCT_P + koct) * MGT + iblk * 8 + mg) * 32 + lane] = o;
    } else if (blk < 2 * PBLK_X + PBLK_W) {
        // W -> B-paired, n = q | k,v interleaved
        int idx = (blk - 2 * PBLK_X) * 256 + tid;    // over KOCT_P*96*32 = 98304
        int lane = idx & 31;
        int p    = (idx >> 5) % NP16_P;
        int koct = idx / (NP16_P * 32);
        int lr = lane >> 2, lq = lane & 3;
        int k0 = koct * 16 + 2 * lq;
        auto wval = [&](int n, int kk) -> float {
            const float* W;
            int c;
            if (n < 512) { W = Wq; c = n; }
            else {
                int m = n - 512;
                c = m >> 1;
                W = (m & 1) ? Wv : Wk;
            }
            return W[(size_t)c * CC + kk];
        };
        int ne = p * 16 + lr, no = ne + 8;
        uint4 o;
        o.x = packh2(wval(ne, k0),     wval(ne, k0 + 1));
        o.y = packh2(wval(ne, k0 + 8), wval(ne, k0 + 9));
        o.z = packh2(wval(no, k0),     wval(no, k0 + 1));
        o.w = packh2(wval(no, k0 + 8), wval(no, k0 + 9));
        g_w4[idx] = o;
    } else {
        // exp(pb) -> A-native (m = i, k = j)
        int t = blk - (2 * PBLK_X + PBLK_W);
        int koct = t / 18, iblk = t % 18;
        int i0 = iblk * 128, j0 = koct * 16;
        #pragma unroll
        for (int r = 0; r < 2; r++) {
            int idx = tid + r * 256;
            int irow = idx >> 2, j4 = (idx & 3) << 2;
            float4 f = *(const float4*)(pb + (size_t)(i0 + irow) * NN + j0 + j4);
            s[j4 + 0][irow] = __expf(f.x);
            s[j4 + 1][irow] = __expf(f.y);
            s[j4 + 2][irow] = __expf(f.z);
            s[j4 + 3][irow] = __expf(f.w);
        }
        __syncthreads();
        const int mg = tid >> 5, lane = tid & 31, lr = lane >> 2, lq = lane & 3;
        const int m = mg * 16 + lr;
        uint4 o;
        o.x = packh2(s[2 * lq][m],     s[2 * lq + 1][m]);
        o.y = packh2(s[2 * lq][m + 8], s[2 * lq + 1][m + 8]);
        o.z = packh2(s[2 * lq + 8][m],     s[2 * lq + 9][m]);
        o.w = packh2(s[2 * lq + 8][m + 8], s[2 * lq + 9][m + 8]);
        g_eb4[((size_t)koct * MGT + iblk * 8 + mg) * 32 + lane] = o;
    }
}

// ---------------------------------------------------------------------------
// fp16 GEMM core: BM=128 BN=128, chunk = 4 k-octs (64 k), 256 thr,
// warps 4(m) x 2(n), warp tile 32x64, 3-stage ring, 2 CTAs/SM.
// Per ka-step: 2x LDS.128 (A) + 4x LDS.128 (B-paired) feed 16 HMMAs.
// ---------------------------------------------------------------------------
#define STG 3
#define A_ST 16384
#define B_ST 16384
#define GEMM_SMEM (STG * (A_ST + B_ST))   // 98304 B

template <int MODE>
__global__ void __launch_bounds__(256, 2)
gemm_f16(const float* __restrict__ bq, const float* __restrict__ bk,
         const float* __restrict__ bv, float* __restrict__ out) {
    extern __shared__ char smem[];
    const uint32_t smb = smem_u32(smem);

    const int b  = blockIdx.z;
    const int m0 = blockIdx.x * 128;
    const int n0 = blockIdx.y * 128;
    const int tid = threadIdx.x;

    const uint4* Ag;
    const uint4* Bg;
    int NP16, nch;
    if (MODE == 0) {
        Ag = ((blockIdx.y < 4) ? g_x4 : g_y4) + (size_t)b * KOCT_P * MGT * 32;
        Bg = g_w4;
        NP16 = NP16_P; nch = KOCT_P / 4;         // 8
    } else {
        Ag = g_eb4;
        Bg = g_kv4 + (size_t)b * KOCT_A * NP16_A * 32;
        NP16 = NP16_A; nch = KOCT_A / 4;         // 36
    }
    const int mg0 = m0 >> 4;
    const int np0 = n0 >> 4;

    const int wid = tid >> 5;
    const int mwg = (wid & 3) * 2;        // m-group base (2 mg = 32 rows/warp)
    const int nw  = (wid >> 2) * 64;      // 2 n-warps
    const int nwp = nw >> 4;              // pair base within tile
    const int lane = tid & 31;
    const int lq = lane & 3;
    const int lr = lane >> 2;

    auto loadAsync = [&](int ch, int st) {
        const uint32_t sA = smb + st * A_ST;
        const uint32_t sB = smb + STG * A_ST + st * B_ST;
        #pragma unroll
        for (int r = 0; r < 4; r++) {
            int ko = ch * 4 + r;
            cp16(sA + r * 4096 + tid * 16,
                 Ag + ((size_t)ko * MGT + mg0) * 32 + tid);
            cp16(sB + r * 4096 + tid * 16,
                 Bg + ((size_t)ko * NP16 + np0) * 32 + tid);
        }
    };

    float acc[2][8][4];
    #pragma unroll
    for (int i = 0; i < 2; i++)
        #pragma unroll
        for (int j = 0; j < 8; j++)
            #pragma unroll
            for (int l = 0; l < 4; l++) acc[i][j][l] = 0.f;

    #pragma unroll
    for (int s = 0; s < STG - 1; s++) {
        loadAsync(s, s);
        CP_COMMIT();
    }

    int st = 0;
    for (int c = 0; c < nch; c++) {
        CP_WAIT(STG - 2);
        __syncthreads();
        if (c + STG - 1 < nch) loadAsync(c + STG - 1, (c + STG - 1) % STG);
        CP_COMMIT();

        const uint4* As4 = (const uint4*)(smem + st * A_ST);
        const uint4* Bs4 = (const uint4*)(smem + STG * A_ST + st * B_ST);
        #pragma unroll
        for (int ka = 0; ka < 4; ka++) {
            uint4 af0 = As4[ka * 256 + mwg * 32 + lane];
            uint4 af1 = As4[ka * 256 + (mwg + 1) * 32 + lane];
            uint4 bp[4];
            #pragma unroll
            for (int pw = 0; pw < 4; pw++)
                bp[pw] = Bs4[ka * 256 + (nwp + pw) * 32 + lane];
            #pragma unroll
            for (int pw = 0; pw < 4; pw++) {
                mma_f16(acc[0][2 * pw],     (const uint32_t*)&af0, &bp[pw].x);
                mma_f16(acc[0][2 * pw + 1], (const uint32_t*)&af0, &bp[pw].z);
                mma_f16(acc[1][2 * pw],     (const uint32_t*)&af1, &bp[pw].x);
                mma_f16(acc[1][2 * pw + 1], (const uint32_t*)&af1, &bp[pw].z);
            }
        }
        st++;
        if (st == STG) st = 0;
    }

    // ------------------------------- Epilogues -----------------------------
    const int mw = (wid & 3) * 32;
    if (MODE == 0) {
        if (n0 < 512) {
            float* sq = g_sq + (size_t)b * NN * CC;
            #pragma unroll
            for (int mi = 0; mi < 2; mi++) {
                #pragma unroll
                for (int ni = 0; ni < 8; ni++) {
                    int row = m0 + mw + 16 * mi + lr;
                    int col = n0 + nw + 8 * ni + 2 * lq;
                    float b0 = bq[col], b1 = bq[col + 1];
                    float* a = acc[mi][ni];
                    float2 v0, v1;
                    v0.x = __fdividef(1.f, 1.f + __expf(-(a[0] + b0)));
                    v0.y = __fdividef(1.f, 1.f + __expf(-(a[1] + b1)));
                    v1.x = __fdividef(1.f, 1.f + __expf(-(a[2] + b0)));
                    v1.y = __fdividef(1.f, 1.f + __expf(-(a[3] + b1)));
                    *(float2*)(sq + (size_t)row * CC + col) = v0;
                    *(float2*)(sq + (size_t)(row + 8) * CC + col) = v1;
                }
            }
        } else {
            // kv region -> attn B-paired [koct_j][pair][lane]
            uint4* kvh = g_kv4 + (size_t)b * KOCT_A * NP16_A * 32;
            const bool evenR = (lr & 1) == 0;
            const int t = lr >> 1;
            #pragma unroll
            for (int mi = 0; mi < 2; mi++) {
                int mb = m0 + mw + 16 * mi;
                int koct = mb >> 4;
                #pragma unroll
                for (int np = 0; np < 4; np++) {
                    int col_e = n0 + nw + 16 * np + 2 * lq - 512;   // ni=2np (even)
                    int ch_e = col_e >> 1;
                    int ch_o = ch_e + 4;                            // col_o = col_e+8
                    float* ae = acc[mi][2 * np];
                    float* ao = acc[mi][2 * np + 1];
                    float bk_e = bk[ch_e], bv_e = bv[ch_e];
                    float bk_o = bk[ch_o], bv_o = bv[ch_o];
                    float e0e  = __expf(ae[0] + bk_e);
                    float ev0e = e0e * (ae[1] + bv_e);
                    float e1e  = __expf(ae[2] + bk_e);
                    float ev1e = e1e * (ae[3] + bv_e);
                    float e0o  = __expf(ao[0] + bk_o);
                    float ev0o = e0o * (ao[1] + bv_o);
                    float e1o  = __expf(ao[2] + bk_o);
                    float ev1o = e1o * (ao[3] + bv_o);
                    float pe0e  = __shfl_xor_sync(0xffffffffu, e0e, 4);
                    float pev0e = __shfl_xor_sync(0xffffffffu, ev0e, 4);
                    float pe1e  = __shfl_xor_sync(0xffffffffu, e1e, 4);
                    float pev1e = __shfl_xor_sync(0xffffffffu, ev1e, 4);
                    float pe0o  = __shfl_xor_sync(0xffffffffu, e0o, 4);
                    float pev0o = __shfl_xor_sync(0xffffffffu, ev0o, 4);
                    float pe1o  = __shfl_xor_sync(0xffffffffu, e1o, 4);
                    float pev1o = __shfl_xor_sync(0xffffffffu, ev1o, 4);
                    if (evenR) {
                        int p = col_e >> 4;
                        int lane_e = (col_e & 7) * 4 + t;
                        uint4 wkv, wek;
                        wkv.x = packh2(ev0e, pev0e);
                        wkv.y = packh2(ev1e, pev1e);
                        wkv.z = packh2(ev0o, pev0o);
                        wkv.w = packh2(ev1o, pev1o);
                        wek.x = packh2(e0e, pe0e);
                        wek.y = packh2(e1e, pe1e);
                        wek.z = packh2(e0o, pe0o);
                        wek.w = packh2(e1o, pe1o);
                        kvh[((size_t)koct * NP16_A + p) * 32 + lane_e]     = wkv;
                        kvh[((size_t)koct * NP16_A + p) * 32 + lane_e + 4] = wek;
                    }
                }
            }
        }
    } else {
        // attn: even col = num, odd = den -> sq * num/den -> transpose -> out
        __syncthreads();
        float* so = (float*)smem;     // [c_local 0..63][m_local 0..127] stride 136
        const float* sq = g_sq + (size_t)b * NN * CC;
        const int gc0 = n0 >> 1;
        #pragma unroll
        for (int mi = 0; mi < 2; mi++) {
            #pragma unroll
            for (int ni = 0; ni < 8; ni++) {
                int rowm = mw + 16 * mi + lr;
                int cl = (nw >> 1) + 4 * ni + lq;
                int gi = m0 + rowm;
                int gc = gc0 + cl;
                float* a = acc[mi][ni];
                float s0 = sq[(size_t)gi * CC + gc];
                float s1 = sq[(size_t)(gi + 8) * CC + gc];
                so[cl * 136 + rowm]     = s0 * __fdividef(a[0], a[1]);
                so[cl * 136 + rowm + 8] = s1 * __fdividef(a[2], a[3]);
            }
        }
        __syncthreads();
        float* o = out + (size_t)b * CC * NN;
        #pragma unroll
        for (int r2 = 0; r2 < 8; r2++) {
            int v = tid + r2 * 256;
            int cl = v >> 5, m4 = (v & 31) << 2;
            float4 val = *(float4*)(so + cl * 136 + m4);
            *(float4*)(o + (size_t)(gc0 + cl) * NN + m0 + m4) = val;
        }
    }
}

// ---------------------------------------------------------------------------
// Launch.  Order: 0 prep_all, 1 proj, 2 attn
// ---------------------------------------------------------------------------
extern "C" void kernel_launch(void* const* d_in, const int* in_sizes, int n_in,
                              void* d_out, int out_size) {
    const float* x  = (const float*)d_in[0];
    const float* y  = (const float*)d_in[1];
    const float* Wq = (const float*)d_in[2];
    const float* bq = (const float*)d_in[3];
    const float* Wk = (const float*)d_in[4];
    const float* bk = (const float*)d_in[5];
    const float* Wv = (const float*)d_in[6];
    const float* bv = (const float*)d_in[7];
    const float* pb = (const float*)d_in[8];
    float* out = (float*)d_out;

    static bool attr_done = false;
    if (!attr_done) {
        cudaFuncSetAttribute(gemm_f16<0>,
                             cudaFuncAttributeMaxDynamicSharedMemorySize, GEMM_SMEM);
        cudaFuncSetAttribute(gemm_f16<1>,
                             cudaFuncAttributeMaxDynamicSharedMemorySize, GEMM_SMEM);
        attr_done = true;
    }

    // 0) all operand prep in one launch
    prep_all<<<PREP_BLOCKS, 256>>>(x, y, Wq, Wk, Wv, pb);

    // 1) fused projection GEMM -> g_sq, g_kv4 (attn B-paired)
    {
        dim3 g(NN / 128, NPROJ / 128, BB);   // (18, 12, 8)
        gemm_f16<0><<<g, 256, GEMM_SMEM>>>(bq, bk, bv, nullptr);
    }

    // 2) attention GEMM + fused final epilogue -> out
    {
        dim3 g(NN / 128, NKV / 128, BB);     // (18, 8, 8)
        gemm_f16<1><<<g, 256, GEMM_SMEM>>>(bq, bk, bv, out);
    }
}